// round 12
// baseline (speedup 1.0000x reference)
#include <cuda_runtime.h>
#include <cstdint>
#include <math.h>

// AttentionAggregator via PIPELINED TMA bulk-copy gathers.
// Model (fits all 10 prior rounds): every LDG/cp.async variant plateaus at
// ~10.2us kernel because gathers funnel through the L1tex miss path
// (~64 outstanding lines/SM x ~300ns). TMA bulk copies bypass L1tex miss
// tracking; R10 proved the engine was idle (tma=2.3%) but the kernel had no
// pipelining. Here each warp owns 2 rows / 2 buffers / 2 mbarriers, fires
// BOTH rows' copies up front, and computes row A while row B flies.
// features: [100000, 256] f32; nodes: [4096] i32; unique_ids: [16384] i32;
// neigh_idx: [4096, 10] i32. out: [4096, 256] f32.

#define N_NODES 4096
#define FDIM    256
#define NSAMP   10
#define WARPS   4
#define ROW_BYTES 1024
#define BUF_BYTES (11 * ROW_BYTES)            // q + 10 embed rows
#define DATA_BYTES (WARPS * 2 * BUF_BYTES)    // 90112 B
#define SMEM_TOTAL (DATA_BYTES + WARPS * 16)  // + 2 mbarriers/warp

__device__ __forceinline__ void bulk_cp_1k(unsigned int dst, const void* src,
                                           unsigned int mbar) {
    asm volatile(
        "cp.async.bulk.shared::cta.global.mbarrier::complete_tx::bytes "
        "[%0], [%1], %2, [%3];"
        :: "r"(dst), "l"(src), "r"((unsigned)ROW_BYTES), "r"(mbar) : "memory");
}

__device__ __forceinline__ void mbar_wait_p0(unsigned int mbar) {
    unsigned int done;
    asm volatile(
        "{\n\t.reg .pred p;\n\t"
        "mbarrier.try_wait.parity.acquire.cta.shared::cta.b64 p, [%1], %2;\n\t"
        "selp.b32 %0, 1, 0, p;\n\t}"
        : "=r"(done) : "r"(mbar), "r"(0u) : "memory");
    if (!done) {
        asm volatile(
            "{\n\t.reg .pred P1;\n\t"
            "WL_%=:\n\t"
            "mbarrier.try_wait.parity.acquire.cta.shared::cta.b64 P1, [%0], %1, 0x989680;\n\t"
            "@P1 bra.uni WD_%=;\n\t"
            "bra.uni WL_%=;\n\t"
            "WD_%=:\n\t}"
            :: "r"(mbar), "r"(0u) : "memory");
    }
}

__device__ __forceinline__ void stcs128(float* p, float4 v) {
    asm volatile("st.global.cs.v4.f32 [%0], {%1,%2,%3,%4};"
                 :: "l"(p), "f"(v.x), "f"(v.y), "f"(v.z), "f"(v.w));
}

// dots + dedup-softmax + weighted aggregate + streaming store, all from SMEM
__device__ __forceinline__ void process_row(const char* buf, unsigned dup,
                                            float* outp, int lane)
{
    const float4* qf = (const float4*)buf;
    const float4 q0 = qf[lane];
    const float4 q1 = qf[lane + 32];

    float dots[NSAMP];
    #pragma unroll
    for (int s = 0; s < NSAMP; s++) {
        const float4* ep = (const float4*)(buf + (1 + s) * ROW_BYTES);
        const float4 b0 = ep[lane];
        const float4 b1 = ep[lane + 32];
        float a = b0.x*q0.x + b0.y*q0.y + b0.z*q0.z + b0.w*q0.w
                + b1.x*q1.x + b1.y*q1.y + b1.z*q1.z + b1.w*q1.w;
        #pragma unroll
        for (int o = 16; o; o >>= 1)
            a += __shfl_xor_sync(0xffffffffu, a, o);
        dots[s] = a;
    }

    float m = -INFINITY;
    #pragma unroll
    for (int s = 0; s < NSAMP; s++)
        if (!((dup >> s) & 1u)) m = fmaxf(m, dots[s]);
    float sum = 0.f;
    #pragma unroll
    for (int s = 0; s < NSAMP; s++) {
        float e = ((dup >> s) & 1u) ? 0.f : __expf(dots[s] - m);
        dots[s] = e;
        sum += e;
    }
    const float inv = 1.f / sum;

    float4 o0 = make_float4(0.f, 0.f, 0.f, 0.f);
    float4 o1 = make_float4(0.f, 0.f, 0.f, 0.f);
    #pragma unroll
    for (int s = 0; s < NSAMP; s++) {
        const float ws = dots[s] * inv;
        const float4* ep = (const float4*)(buf + (1 + s) * ROW_BYTES);
        const float4 b0 = ep[lane];
        const float4 b1 = ep[lane + 32];
        o0.x += ws*b0.x; o0.y += ws*b0.y;
        o0.z += ws*b0.z; o0.w += ws*b0.w;
        o1.x += ws*b1.x; o1.y += ws*b1.y;
        o1.z += ws*b1.z; o1.w += ws*b1.w;
    }
    stcs128(outp + lane * 4, o0);
    stcs128(outp + (lane + 32) * 4, o1);
}

__global__ __launch_bounds__(WARPS * 32)
void attn_agg_kernel(const float* __restrict__ feat,
                     const int*   __restrict__ nodes,
                     const int*   __restrict__ uids,
                     const int*   __restrict__ nidx,
                     float*       __restrict__ out)
{
    extern __shared__ char smem[];
    const int warp = threadIdx.x >> 5;
    const int lane = threadIdx.x & 31;
    const int row0 = (blockIdx.x * WARPS + warp) * 2;   // rows A=row0, B=row0+1

    char* buf0 = smem + warp * 2 * BUF_BYTES;
    char* buf1 = buf0 + BUF_BYTES;
    const unsigned int s0 = (unsigned int)__cvta_generic_to_shared(buf0);
    const unsigned int s1 = (unsigned int)__cvta_generic_to_shared(buf1);
    const unsigned int mb0 =
        (unsigned int)__cvta_generic_to_shared(smem + DATA_BYTES + warp * 16);
    const unsigned int mb1 = mb0 + 8;

    // --- indices for both rows (80B contiguous -> 5x int4) ---
    int cols[2 * NSAMP];
    {
        const int4* np = (const int4*)(nidx + (size_t)row0 * NSAMP);
        #pragma unroll
        for (int i = 0; i < 5; i++) {
            int4 v = np[i];
            cols[4*i+0] = v.x; cols[4*i+1] = v.y;
            cols[4*i+2] = v.z; cols[4*i+3] = v.w;
        }
    }
    int uid[2 * NSAMP];
    #pragma unroll
    for (int s = 0; s < 2 * NSAMP; s++)
        uid[s] = uids[cols[s]];
    const int2 nn = *(const int2*)(nodes + row0);

    // --- barriers, then fire BOTH rows' copies (22.5KB outstanding/warp) ---
    if (lane == 0) {
        asm volatile("mbarrier.init.shared.b64 [%0], %1;" :: "r"(mb0), "r"(1) : "memory");
        asm volatile("mbarrier.init.shared.b64 [%0], %1;" :: "r"(mb1), "r"(1) : "memory");
    }
    __syncwarp();

    if (lane == 0) {
        asm volatile("mbarrier.arrive.expect_tx.shared.b64 _, [%0], %1;"
                     :: "r"(mb0), "r"((unsigned)BUF_BYTES) : "memory");
        bulk_cp_1k(s0, feat + (size_t)nn.x * FDIM, mb0);
        #pragma unroll
        for (int s = 0; s < NSAMP; s++)
            bulk_cp_1k(s0 + (unsigned)(1 + s) * ROW_BYTES,
                       feat + (size_t)uid[s] * FDIM, mb0);

        asm volatile("mbarrier.arrive.expect_tx.shared.b64 _, [%0], %1;"
                     :: "r"(mb1), "r"((unsigned)BUF_BYTES) : "memory");
        bulk_cp_1k(s1, feat + (size_t)nn.y * FDIM, mb1);
        #pragma unroll
        for (int s = 0; s < NSAMP; s++)
            bulk_cp_1k(s1 + (unsigned)(1 + s) * ROW_BYTES,
                       feat + (size_t)uid[NSAMP + s] * FDIM, mb1);
    }

    // --- dedup masks while copies fly (dense mask counts repeats once) ---
    unsigned dup[2] = {0u, 0u};
    #pragma unroll
    for (int r = 0; r < 2; r++)
        #pragma unroll
        for (int s = 1; s < NSAMP; s++) {
            bool d = false;
            #pragma unroll
            for (int t = 0; t < NSAMP; t++)
                if (t < s) d |= (cols[r*NSAMP+t] == cols[r*NSAMP+s]);
            if (d) dup[r] |= (1u << s);
        }

    // --- row A (row B's copies still in flight), then row B ---
    mbar_wait_p0(mb0);
    process_row(buf0, dup[0], out + (size_t)row0 * FDIM, lane);

    mbar_wait_p0(mb1);
    process_row(buf1, dup[1], out + (size_t)(row0 + 1) * FDIM, lane);
}

extern "C" void kernel_launch(void* const* d_in, const int* in_sizes, int n_in,
                              void* d_out, int out_size)
{
    const float* feat  = (const float*)d_in[0];
    const int*   nodes = (const int*)  d_in[1];
    const int*   uids  = (const int*)  d_in[2];
    const int*   nidx  = (const int*)  d_in[3];
    float*       out   = (float*)d_out;
    (void)in_sizes; (void)n_in; (void)out_size;

    cudaFuncSetAttribute(attn_agg_kernel,
                         cudaFuncAttributeMaxDynamicSharedMemorySize,
                         SMEM_TOTAL);
    attn_agg_kernel<<<N_NODES / (WARPS * 2), WARPS * 32, SMEM_TOTAL>>>(
        feat, nodes, uids, nidx, out);
}

// round 13
// speedup vs baseline: 1.1940x; 1.1940x over previous
#include <cuda_runtime.h>
#include <cstdint>
#include <math.h>

// AttentionAggregator: DUAL-PATH gather. Row A through the LSU/L1tex path
// (22 register-resident LDG.128 — capped by the ~55-64 SM-wide outstanding
// LDG limit), row B simultaneously through the TMA engine (11 bulk copies
// into SMEM — bypasses L1tex miss tracking entirely). The two hardware
// gather paths each plateau alone at ~4TB/s (10 rounds of evidence); this
// kernel runs them concurrently. 1 warp per block for wave balance (R9's
// best-kernel shape), streaming stores for the never-reread output.
// features: [100000, 256] f32; nodes: [4096] i32; unique_ids: [16384] i32;
// neigh_idx: [4096, 10] i32. out: [4096, 256] f32.

#define N_NODES 4096
#define FDIM    256
#define NSAMP   10
#define ROW_BYTES 1024
#define BUF_BYTES (11 * ROW_BYTES)   // q_B + 10 embed rows = 11264 B

__device__ __forceinline__ void bulk_cp_1k(unsigned int dst, const void* src,
                                           unsigned int mbar) {
    asm volatile(
        "cp.async.bulk.shared::cta.global.mbarrier::complete_tx::bytes "
        "[%0], [%1], %2, [%3];"
        :: "r"(dst), "l"(src), "r"((unsigned)ROW_BYTES), "r"(mbar) : "memory");
}

__device__ __forceinline__ void mbar_wait_p0(unsigned int mbar) {
    unsigned int done;
    asm volatile(
        "{\n\t.reg .pred p;\n\t"
        "mbarrier.try_wait.parity.acquire.cta.shared::cta.b64 p, [%1], %2;\n\t"
        "selp.b32 %0, 1, 0, p;\n\t}"
        : "=r"(done) : "r"(mbar), "r"(0u) : "memory");
    if (!done) {
        asm volatile(
            "{\n\t.reg .pred P1;\n\t"
            "WL_%=:\n\t"
            "mbarrier.try_wait.parity.acquire.cta.shared::cta.b64 P1, [%0], %1, 0x989680;\n\t"
            "@P1 bra.uni WD_%=;\n\t"
            "bra.uni WL_%=;\n\t"
            "WD_%=:\n\t}"
            :: "r"(mbar), "r"(0u) : "memory");
    }
}

__device__ __forceinline__ void stcs128(float* p, float4 v) {
    asm volatile("st.global.cs.v4.f32 [%0], {%1,%2,%3,%4};"
                 :: "l"(p), "f"(v.x), "f"(v.y), "f"(v.z), "f"(v.w));
}

__global__ __launch_bounds__(32)
void attn_agg_kernel(const float* __restrict__ feat,
                     const int*   __restrict__ nodes,
                     const int*   __restrict__ uids,
                     const int*   __restrict__ nidx,
                     float*       __restrict__ out)
{
    const int lane = threadIdx.x & 31;
    const int row0 = blockIdx.x * 2;              // A=row0, B=row0+1

    __shared__ __align__(16) char bbuf[BUF_BYTES];
    __shared__ __align__(8) unsigned long long mbar_storage;
    const unsigned int sdata = (unsigned int)__cvta_generic_to_shared(bbuf);
    const unsigned int smbar =
        (unsigned int)__cvta_generic_to_shared(&mbar_storage);

    // --- indices for both rows (80B contiguous -> 5x int4) ---
    int cols[2 * NSAMP];
    {
        const int4* np = (const int4*)(nidx + (size_t)row0 * NSAMP);
        #pragma unroll
        for (int i = 0; i < 5; i++) {
            int4 v = np[i];
            cols[4*i+0] = v.x; cols[4*i+1] = v.y;
            cols[4*i+2] = v.z; cols[4*i+3] = v.w;
        }
    }
    int uid[2 * NSAMP];
    #pragma unroll
    for (int s = 0; s < 2 * NSAMP; s++)
        uid[s] = uids[cols[s]];
    const int2 nn = *(const int2*)(nodes + row0);

    // --- fire row B down the TMA path first (engine starts now) ---
    if (lane == 0) {
        asm volatile("mbarrier.init.shared.b64 [%0], %1;"
                     :: "r"(smbar), "r"(1) : "memory");
        asm volatile("mbarrier.arrive.expect_tx.shared.b64 _, [%0], %1;"
                     :: "r"(smbar), "r"((unsigned)BUF_BYTES) : "memory");
        bulk_cp_1k(sdata, feat + (size_t)nn.y * FDIM, smbar);
        #pragma unroll
        for (int s = 0; s < NSAMP; s++)
            bulk_cp_1k(sdata + (unsigned)(1 + s) * ROW_BYTES,
                       feat + (size_t)uid[NSAMP + s] * FDIM, smbar);
    }
    __syncwarp();

    // --- row A down the LSU path: 22 independent LDG.128, reg-resident ---
    const float4* qpA = (const float4*)(feat + (size_t)nn.x * FDIM);
    const float4 qA0 = qpA[lane];
    const float4 qA1 = qpA[lane + 32];

    float4 a0[NSAMP], a1[NSAMP];
    #pragma unroll
    for (int s = 0; s < NSAMP; s++) {
        const float4* ep = (const float4*)(feat + (size_t)uid[s] * FDIM);
        a0[s] = ep[lane];
        a1[s] = ep[lane + 32];
    }

    // --- dup masks while both streams fly (mask counts repeated cols once) ---
    unsigned dup[2] = {0u, 0u};
    #pragma unroll
    for (int r = 0; r < 2; r++)
        #pragma unroll
        for (int s = 1; s < NSAMP; s++) {
            bool d = false;
            #pragma unroll
            for (int t = 0; t < NSAMP; t++)
                if (t < s) d |= (cols[r*NSAMP+t] == cols[r*NSAMP+s]);
            if (d) dup[r] |= (1u << s);
        }

    // --- row A: dots + reduce + softmax + aggregate + streaming store ---
    float dots[NSAMP];
    #pragma unroll
    for (int s = 0; s < NSAMP; s++) {
        float a = a0[s].x*qA0.x + a0[s].y*qA0.y + a0[s].z*qA0.z + a0[s].w*qA0.w
                + a1[s].x*qA1.x + a1[s].y*qA1.y + a1[s].z*qA1.z + a1[s].w*qA1.w;
        #pragma unroll
        for (int o = 16; o; o >>= 1)
            a += __shfl_xor_sync(0xffffffffu, a, o);
        dots[s] = a;
    }
    {
        float m = -INFINITY;
        #pragma unroll
        for (int s = 0; s < NSAMP; s++)
            if (!((dup[0] >> s) & 1u)) m = fmaxf(m, dots[s]);
        float sum = 0.f;
        #pragma unroll
        for (int s = 0; s < NSAMP; s++) {
            float e = ((dup[0] >> s) & 1u) ? 0.f : __expf(dots[s] - m);
            dots[s] = e; sum += e;
        }
        const float inv = 1.f / sum;

        float4 o0 = make_float4(0.f,0.f,0.f,0.f);
        float4 o1 = make_float4(0.f,0.f,0.f,0.f);
        #pragma unroll
        for (int s = 0; s < NSAMP; s++) {
            const float ws = dots[s] * inv;
            o0.x += ws*a0[s].x; o0.y += ws*a0[s].y;
            o0.z += ws*a0[s].z; o0.w += ws*a0[s].w;
            o1.x += ws*a1[s].x; o1.y += ws*a1[s].y;
            o1.z += ws*a1[s].z; o1.w += ws*a1[s].w;
        }
        float* op = out + (size_t)row0 * FDIM;
        stcs128(op + lane * 4, o0);
        stcs128(op + (lane + 32) * 4, o1);
    }

    // --- row B: TMA buffer should have landed during row A's work ---
    mbar_wait_p0(smbar);

    const float4* qf = (const float4*)bbuf;
    const float4 qB0 = qf[lane];
    const float4 qB1 = qf[lane + 32];

    #pragma unroll
    for (int s = 0; s < NSAMP; s++) {
        const float4* ep = (const float4*)(bbuf + (1 + s) * ROW_BYTES);
        const float4 b0 = ep[lane];
        const float4 b1 = ep[lane + 32];
        float a = b0.x*qB0.x + b0.y*qB0.y + b0.z*qB0.z + b0.w*qB0.w
                + b1.x*qB1.x + b1.y*qB1.y + b1.z*qB1.z + b1.w*qB1.w;
        #pragma unroll
        for (int o = 16; o; o >>= 1)
            a += __shfl_xor_sync(0xffffffffu, a, o);
        dots[s] = a;
    }
    {
        float m = -INFINITY;
        #pragma unroll
        for (int s = 0; s < NSAMP; s++)
            if (!((dup[1] >> s) & 1u)) m = fmaxf(m, dots[s]);
        float sum = 0.f;
        #pragma unroll
        for (int s = 0; s < NSAMP; s++) {
            float e = ((dup[1] >> s) & 1u) ? 0.f : __expf(dots[s] - m);
            dots[s] = e; sum += e;
        }
        const float inv = 1.f / sum;

        float4 o0 = make_float4(0.f,0.f,0.f,0.f);
        float4 o1 = make_float4(0.f,0.f,0.f,0.f);
        #pragma unroll
        for (int s = 0; s < NSAMP; s++) {
            const float ws = dots[s] * inv;
            const float4* ep = (const float4*)(bbuf + (1 + s) * ROW_BYTES);
            const float4 b0 = ep[lane];
            const float4 b1 = ep[lane + 32];
            o0.x += ws*b0.x; o0.y += ws*b0.y;
            o0.z += ws*b0.z; o0.w += ws*b0.w;
            o1.x += ws*b1.x; o1.y += ws*b1.y;
            o1.z += ws*b1.z; o1.w += ws*b1.w;
        }
        float* op = out + (size_t)(row0 + 1) * FDIM;
        stcs128(op + lane * 4, o0);
        stcs128(op + (lane + 32) * 4, o1);
    }
}

extern "C" void kernel_launch(void* const* d_in, const int* in_sizes, int n_in,
                              void* d_out, int out_size)
{
    const float* feat  = (const float*)d_in[0];
    const int*   nodes = (const int*)  d_in[1];
    const int*   uids  = (const int*)  d_in[2];
    const int*   nidx  = (const int*)  d_in[3];
    float*       out   = (float*)d_out;
    (void)in_sizes; (void)n_in; (void)out_size;

    attn_agg_kernel<<<N_NODES / 2, 32>>>(feat, nodes, uids, nidx, out);
}